// round 1
// baseline (speedup 1.0000x reference)
#include <cuda_runtime.h>
#include <math.h>

// Fused MHA: O = softmax(Q*scale @ K^T + bias) @ V
// B=2, H=16, S=2048, D=64, fp32 in/out, bias [S,S] broadcast over (B,H).
//
// Baseline: fp32 flash-attention, BM=BN=64, 128 threads (16x8), each thread
// owns an 8(M)x4(N) micro-tile. Online softmax; row groups live on 16-lane
// half-warps so reductions are shfl_xor {1,2,4,8}.

namespace {
constexpr int S_LEN = 2048;
constexpr int D     = 64;
constexpr int BM    = 64;
constexpr int BN    = 64;
constexpr int NT    = 128;   // threads per CTA
constexpr int SP    = 68;    // padded row stride (floats), 16B-aligned
constexpr int SMEM_BYTES = 4 * BM * SP * (int)sizeof(float);  // q,k,v,p tiles = 69632 B
}

__global__ __launch_bounds__(NT) void mha_fa_kernel(
    const float* __restrict__ Q, const float* __restrict__ K,
    const float* __restrict__ V, const float* __restrict__ Bias,
    float* __restrict__ O)
{
    extern __shared__ float sh[];
    float* q_sh = sh;                 // [BM][SP]
    float* k_sh = sh + 1 * BM * SP;   // [BN][SP]
    float* v_sh = sh + 2 * BM * SP;   // [BN][SP]
    float* p_sh = sh + 3 * BM * SP;   // [BM][SP]

    const int tid = threadIdx.x;
    const int tx  = tid & 15;   // 0..15 -> N / D columns (4 each)
    const int ty  = tid >> 4;   // 0..7  -> M rows (8 each)
    const int q0  = blockIdx.x * BM;
    const size_t base = (size_t)blockIdx.y * S_LEN * D;   // (b,h) plane

    // ---- load Q tile, pre-scaled by 1/sqrt(D) ----
    {
        const float4* g = reinterpret_cast<const float4*>(Q + base + (size_t)q0 * D);
        #pragma unroll
        for (int it = 0; it < (BM * D / 4) / NT; it++) {
            int v4 = tid + it * NT;
            int r = v4 >> 4, c4 = v4 & 15;     // D/4 = 16 float4 per row
            float4 val = g[v4];
            val.x *= 0.125f; val.y *= 0.125f; val.z *= 0.125f; val.w *= 0.125f;
            *reinterpret_cast<float4*>(&q_sh[r * SP + c4 * 4]) = val;
        }
    }

    float acc[8][4];
    float m_i[8], l_i[8];
    #pragma unroll
    for (int ii = 0; ii < 8; ii++) {
        m_i[ii] = -INFINITY; l_i[ii] = 0.f;
        #pragma unroll
        for (int jj = 0; jj < 4; jj++) acc[ii][jj] = 0.f;
    }

    const int row0 = ty * 8;
    const int col0 = tx * 4;

    for (int kt = 0; kt < S_LEN / BN; kt++) {
        const int k0 = kt * BN;

        __syncthreads();  // previous PV reads of v_sh/p_sh done (also covers q_sh store)
        // ---- load K,V tiles ----
        {
            const float4* gk = reinterpret_cast<const float4*>(K + base + (size_t)k0 * D);
            const float4* gv = reinterpret_cast<const float4*>(V + base + (size_t)k0 * D);
            #pragma unroll
            for (int it = 0; it < (BN * D / 4) / NT; it++) {
                int v4 = tid + it * NT;
                int r = v4 >> 4, c4 = v4 & 15;
                *reinterpret_cast<float4*>(&k_sh[r * SP + c4 * 4]) = gk[v4];
                *reinterpret_cast<float4*>(&v_sh[r * SP + c4 * 4]) = gv[v4];
            }
        }
        __syncthreads();

        // ---- scores: s = bias + (Q*scale) @ K^T ----
        float s[8][4];
        #pragma unroll
        for (int ii = 0; ii < 8; ii++) {
            const float4 bv = *reinterpret_cast<const float4*>(
                Bias + (size_t)(q0 + row0 + ii) * S_LEN + k0 + col0);
            s[ii][0] = bv.x; s[ii][1] = bv.y; s[ii][2] = bv.z; s[ii][3] = bv.w;
        }
        #pragma unroll 4
        for (int d = 0; d < D; d++) {
            float qf[8], kf[4];
            #pragma unroll
            for (int ii = 0; ii < 8; ii++) qf[ii] = q_sh[(row0 + ii) * SP + d];
            #pragma unroll
            for (int jj = 0; jj < 4; jj++) kf[jj] = k_sh[(col0 + jj) * SP + d];
            #pragma unroll
            for (int ii = 0; ii < 8; ii++)
                #pragma unroll
                for (int jj = 0; jj < 4; jj++)
                    s[ii][jj] = fmaf(qf[ii], kf[jj], s[ii][jj]);
        }

        // ---- online softmax update ----
        #pragma unroll
        for (int ii = 0; ii < 8; ii++) {
            float mx = fmaxf(fmaxf(s[ii][0], s[ii][1]), fmaxf(s[ii][2], s[ii][3]));
            #pragma unroll
            for (int off = 1; off < 16; off <<= 1)
                mx = fmaxf(mx, __shfl_xor_sync(0xFFFFFFFFu, mx, off, 32));
            const float m_new = fmaxf(m_i[ii], mx);
            const float corr  = __expf(m_i[ii] - m_new);   // exp(-inf)=0 on first tile
            float p[4], rs = 0.f;
            #pragma unroll
            for (int jj = 0; jj < 4; jj++) {
                p[jj] = __expf(s[ii][jj] - m_new);
                rs += p[jj];
            }
            #pragma unroll
            for (int off = 1; off < 16; off <<= 1)
                rs += __shfl_xor_sync(0xFFFFFFFFu, rs, off, 32);
            l_i[ii] = l_i[ii] * corr + rs;
            m_i[ii] = m_new;
            #pragma unroll
            for (int jj = 0; jj < 4; jj++) acc[ii][jj] *= corr;
            #pragma unroll
            for (int jj = 0; jj < 4; jj++)
                p_sh[(row0 + ii) * SP + col0 + jj] = p[jj];
        }
        __syncthreads();

        // ---- PV: acc += P @ V ----
        #pragma unroll 2
        for (int j = 0; j < BN; j++) {
            float pf[8];
            #pragma unroll
            for (int ii = 0; ii < 8; ii++) pf[ii] = p_sh[(row0 + ii) * SP + j];
            const float4 vv = *reinterpret_cast<const float4*>(&v_sh[j * SP + col0]);
            #pragma unroll
            for (int ii = 0; ii < 8; ii++) {
                acc[ii][0] = fmaf(pf[ii], vv.x, acc[ii][0]);
                acc[ii][1] = fmaf(pf[ii], vv.y, acc[ii][1]);
                acc[ii][2] = fmaf(pf[ii], vv.z, acc[ii][2]);
                acc[ii][3] = fmaf(pf[ii], vv.w, acc[ii][3]);
            }
        }
    }

    // ---- normalize and write ----
    #pragma unroll
    for (int ii = 0; ii < 8; ii++) {
        const float inv = 1.0f / l_i[ii];
        float4 o;
        o.x = acc[ii][0] * inv; o.y = acc[ii][1] * inv;
        o.z = acc[ii][2] * inv; o.w = acc[ii][3] * inv;
        *reinterpret_cast<float4*>(
            &O[base + (size_t)(q0 + row0 + ii) * D + col0]) = o;
    }
}

extern "C" void kernel_launch(void* const* d_in, const int* in_sizes, int n_in,
                              void* d_out, int out_size) {
    const float* Q    = (const float*)d_in[0];
    const float* K    = (const float*)d_in[1];
    const float* V    = (const float*)d_in[2];
    const float* Bias = (const float*)d_in[3];
    float* O = (float*)d_out;

    const int BH = in_sizes[0] / (S_LEN * D);   // 32 for B=2,H=16

    cudaFuncSetAttribute(mha_fa_kernel,
                         cudaFuncAttributeMaxDynamicSharedMemorySize, SMEM_BYTES);
    dim3 grid(S_LEN / BM, BH);
    mha_fa_kernel<<<grid, NT, SMEM_BYTES>>>(Q, K, V, Bias, O);
}

// round 2
// speedup vs baseline: 5.2096x; 5.2096x over previous
#include <cuda_runtime.h>
#include <math.h>

// Fused MHA: O = softmax(Q*scale @ K^T + bias) @ V
// B=2, H=16, S=2048, D=64, fp32 in/out, bias [S,S] broadcast over (B,H).
//
// Round 2: TF32 mma.sync.m16n8k8 flash attention.
// CTA = 128 threads (4 warps), BM=BN=64. Each warp owns 16 query rows.
// Q/K/P tiles in smem stride 68 (=> fragment LDS lane addr 4*(l/4)+l%4, conflict-free),
// V tile stride 72 (=> lane addr 8*(l%4)+l/4, conflict-free).
// Scores/O accumulate fp32 in mma C fragments; online softmax on C layout
// (row groups = 4 consecutive lanes -> shfl_xor {1,2}).

namespace {
constexpr int S_LEN = 2048;
constexpr int D     = 64;
constexpr int BM    = 64;
constexpr int BN    = 64;
constexpr int NT    = 128;
constexpr int SPA   = 68;   // stride (floats) for q,k,p tiles
constexpr int SPV   = 72;   // stride (floats) for v tile
constexpr int SMEM_FLOATS = 3 * BM * SPA + BN * SPV;
constexpr int SMEM_BYTES  = SMEM_FLOATS * (int)sizeof(float);   // 70656 B
}

__device__ __forceinline__ float f2tf32(float x) {
    unsigned u;
    asm("cvt.rna.tf32.f32 %0, %1;" : "=r"(u) : "f"(x));
    return __uint_as_float(u);
}

__device__ __forceinline__ void mma8(float* c, const unsigned* a, const unsigned* b) {
    asm volatile(
        "mma.sync.aligned.m16n8k8.row.col.f32.tf32.tf32.f32 "
        "{%0,%1,%2,%3}, {%4,%5,%6,%7}, {%8,%9}, {%0,%1,%2,%3};"
        : "+f"(c[0]), "+f"(c[1]), "+f"(c[2]), "+f"(c[3])
        : "r"(a[0]), "r"(a[1]), "r"(a[2]), "r"(a[3]), "r"(b[0]), "r"(b[1]));
}

__global__ __launch_bounds__(NT) void mha_tf32_kernel(
    const float* __restrict__ Q, const float* __restrict__ K,
    const float* __restrict__ V, const float* __restrict__ Bias,
    float* __restrict__ O)
{
    extern __shared__ float sh[];
    float* q_sh = sh;                    // [BM][SPA]
    float* k_sh = sh + BM * SPA;         // [BN][SPA]
    float* p_sh = sh + 2 * BM * SPA;     // [BM][SPA]
    float* v_sh = sh + 3 * BM * SPA;     // [BN][SPV]

    const int tid = threadIdx.x;
    const int w   = tid >> 5;
    const int l   = tid & 31;
    const int rt  = l >> 2;    // l/4
    const int cq  = l & 3;     // l%4
    const int m0  = w * 16;    // warp's first query row in tile

    const int q0 = blockIdx.x * BM;
    const size_t base = (size_t)blockIdx.y * S_LEN * D;

    // ---- load Q tile once, scaled by 1/sqrt(D), converted to tf32 bits ----
    {
        const float4* gq = reinterpret_cast<const float4*>(Q + base + (size_t)q0 * D);
        #pragma unroll
        for (int it = 0; it < (BM * D / 4) / NT; it++) {
            int idx = tid + it * NT;
            int r = idx >> 4, c4 = idx & 15;
            float4 v = gq[idx];
            float4 o;
            o.x = f2tf32(v.x * 0.125f);
            o.y = f2tf32(v.y * 0.125f);
            o.z = f2tf32(v.z * 0.125f);
            o.w = f2tf32(v.w * 0.125f);
            *reinterpret_cast<float4*>(&q_sh[r * SPA + c4 * 4]) = o;
        }
    }

    float c_o[8][4];
    #pragma unroll
    for (int nb = 0; nb < 8; nb++)
        #pragma unroll
        for (int j = 0; j < 4; j++) c_o[nb][j] = 0.f;
    float m_lo = -INFINITY, m_hi = -INFINITY;
    float l_lo = 0.f, l_hi = 0.f;

    for (int kt = 0; kt < S_LEN / BN; kt++) {
        const int k0 = kt * BN;

        __syncthreads();   // previous tile's v_sh/k_sh reads done
        // ---- load K,V tiles (tf32) ----
        {
            const float4* gk = reinterpret_cast<const float4*>(K + base + (size_t)k0 * D);
            const float4* gv = reinterpret_cast<const float4*>(V + base + (size_t)k0 * D);
            #pragma unroll
            for (int it = 0; it < (BN * D / 4) / NT; it++) {
                int idx = tid + it * NT;
                int r = idx >> 4, c4 = idx & 15;
                float4 kv = gk[idx];
                float4 ko;
                ko.x = f2tf32(kv.x); ko.y = f2tf32(kv.y);
                ko.z = f2tf32(kv.z); ko.w = f2tf32(kv.w);
                *reinterpret_cast<float4*>(&k_sh[r * SPA + c4 * 4]) = ko;
                float4 vv = gv[idx];
                float4 vo;
                vo.x = f2tf32(vv.x); vo.y = f2tf32(vv.y);
                vo.z = f2tf32(vv.z); vo.w = f2tf32(vv.w);
                *reinterpret_cast<float4*>(&v_sh[r * SPV + c4 * 4]) = vo;
            }
        }
        __syncthreads();

        // ---- scores init from bias (C-fragment layout) ----
        float c_s[8][4];
        {
            const float* brow = Bias + (size_t)(q0 + m0 + rt) * S_LEN + k0 + 2 * cq;
            #pragma unroll
            for (int nb = 0; nb < 8; nb++) {
                float2 blo = *reinterpret_cast<const float2*>(brow + 8 * nb);
                float2 bhi = *reinterpret_cast<const float2*>(brow + 8 * S_LEN + 8 * nb);
                c_s[nb][0] = blo.x; c_s[nb][1] = blo.y;
                c_s[nb][2] = bhi.x; c_s[nb][3] = bhi.y;
            }
        }

        // ---- QK^T: 8 k-steps x 8 n-blocks of m16n8k8 ----
        #pragma unroll
        for (int ks = 0; ks < 8; ks++) {
            unsigned a[4];
            const float* qr = &q_sh[(m0 + rt) * SPA + 8 * ks + cq];
            a[0] = __float_as_uint(qr[0]);
            a[1] = __float_as_uint(qr[8 * SPA]);
            a[2] = __float_as_uint(qr[4]);
            a[3] = __float_as_uint(qr[8 * SPA + 4]);
            #pragma unroll
            for (int nb = 0; nb < 8; nb++) {
                unsigned b[2];
                const float* kr = &k_sh[(8 * nb + rt) * SPA + 8 * ks + cq];
                b[0] = __float_as_uint(kr[0]);
                b[1] = __float_as_uint(kr[4]);
                mma8(c_s[nb], a, b);
            }
        }

        // ---- online softmax (rows rt and rt+8; group = 4 lanes, shfl 1,2) ----
        float mx_lo = -INFINITY, mx_hi = -INFINITY;
        #pragma unroll
        for (int nb = 0; nb < 8; nb++) {
            mx_lo = fmaxf(mx_lo, fmaxf(c_s[nb][0], c_s[nb][1]));
            mx_hi = fmaxf(mx_hi, fmaxf(c_s[nb][2], c_s[nb][3]));
        }
        #pragma unroll
        for (int off = 1; off < 4; off <<= 1) {
            mx_lo = fmaxf(mx_lo, __shfl_xor_sync(0xFFFFFFFFu, mx_lo, off, 32));
            mx_hi = fmaxf(mx_hi, __shfl_xor_sync(0xFFFFFFFFu, mx_hi, off, 32));
        }
        const float mn_lo = fmaxf(m_lo, mx_lo);
        const float mn_hi = fmaxf(m_hi, mx_hi);
        const float corr_lo = __expf(m_lo - mn_lo);
        const float corr_hi = __expf(m_hi - mn_hi);
        float rs_lo = 0.f, rs_hi = 0.f;
        #pragma unroll
        for (int nb = 0; nb < 8; nb++) {
            c_s[nb][0] = __expf(c_s[nb][0] - mn_lo);
            c_s[nb][1] = __expf(c_s[nb][1] - mn_lo);
            c_s[nb][2] = __expf(c_s[nb][2] - mn_hi);
            c_s[nb][3] = __expf(c_s[nb][3] - mn_hi);
            rs_lo += c_s[nb][0] + c_s[nb][1];
            rs_hi += c_s[nb][2] + c_s[nb][3];
        }
        #pragma unroll
        for (int off = 1; off < 4; off <<= 1) {
            rs_lo += __shfl_xor_sync(0xFFFFFFFFu, rs_lo, off, 32);
            rs_hi += __shfl_xor_sync(0xFFFFFFFFu, rs_hi, off, 32);
        }
        l_lo = l_lo * corr_lo + rs_lo;  m_lo = mn_lo;
        l_hi = l_hi * corr_hi + rs_hi;  m_hi = mn_hi;
        #pragma unroll
        for (int nb = 0; nb < 8; nb++) {
            c_o[nb][0] *= corr_lo; c_o[nb][1] *= corr_lo;
            c_o[nb][2] *= corr_hi; c_o[nb][3] *= corr_hi;
        }

        // ---- store P (tf32) to warp-private smem rows ----
        {
            float* pr = &p_sh[(m0 + rt) * SPA + 2 * cq];
            #pragma unroll
            for (int nb = 0; nb < 8; nb++) {
                float2 lo; lo.x = f2tf32(c_s[nb][0]); lo.y = f2tf32(c_s[nb][1]);
                *reinterpret_cast<float2*>(pr + 8 * nb) = lo;
                float2 hi; hi.x = f2tf32(c_s[nb][2]); hi.y = f2tf32(c_s[nb][3]);
                *reinterpret_cast<float2*>(pr + 8 * SPA + 8 * nb) = hi;
            }
        }
        __syncwarp();

        // ---- PV: acc += P @ V ----
        #pragma unroll
        for (int ks = 0; ks < 8; ks++) {
            unsigned a[4];
            const float* pr = &p_sh[(m0 + rt) * SPA + 8 * ks + cq];
            a[0] = __float_as_uint(pr[0]);
            a[1] = __float_as_uint(pr[8 * SPA]);
            a[2] = __float_as_uint(pr[4]);
            a[3] = __float_as_uint(pr[8 * SPA + 4]);
            #pragma unroll
            for (int nb = 0; nb < 8; nb++) {
                unsigned b[2];
                const float* vr = &v_sh[(8 * ks + cq) * SPV + 8 * nb + rt];
                b[0] = __float_as_uint(vr[0]);
                b[1] = __float_as_uint(vr[4 * SPV]);
                mma8(c_o[nb], a, b);
            }
        }
    }

    // ---- normalize, write O ----
    const float inv_lo = 1.0f / l_lo;
    const float inv_hi = 1.0f / l_hi;
    float* orow = O + base + (size_t)(q0 + m0 + rt) * D + 2 * cq;
    #pragma unroll
    for (int nb = 0; nb < 8; nb++) {
        float2 lo; lo.x = c_o[nb][0] * inv_lo; lo.y = c_o[nb][1] * inv_lo;
        *reinterpret_cast<float2*>(orow + 8 * nb) = lo;
        float2 hi; hi.x = c_o[nb][2] * inv_hi; hi.y = c_o[nb][3] * inv_hi;
        *reinterpret_cast<float2*>(orow + 8 * D + 8 * nb) = hi;
    }
}

extern "C" void kernel_launch(void* const* d_in, const int* in_sizes, int n_in,
                              void* d_out, int out_size) {
    const float* Q    = (const float*)d_in[0];
    const float* K    = (const float*)d_in[1];
    const float* V    = (const float*)d_in[2];
    const float* Bias = (const float*)d_in[3];
    float* O = (float*)d_out;

    const int BH = in_sizes[0] / (S_LEN * D);   // 32 for B=2,H=16

    cudaFuncSetAttribute(mha_tf32_kernel,
                         cudaFuncAttributeMaxDynamicSharedMemorySize, SMEM_BYTES);
    dim3 grid(S_LEN / BM, BH);
    mha_tf32_kernel<<<grid, NT, SMEM_BYTES>>>(Q, K, V, Bias, O);
}

// round 3
// speedup vs baseline: 5.6071x; 1.0763x over previous
#include <cuda_runtime.h>
#include <math.h>

// Fused MHA: O = softmax(Q*scale @ K^T + bias) @ V
// B=2, H=16, S=2048, D=64, fp32 in/out, bias [S,S] broadcast over (B,H).
//
// Round 3: TF32 mma.sync.m16n8k8, BM=128 / BN=64, 128 threads (4 warps),
// each warp owns 32 query rows (2 m-blocks of 16). Doubling rows-per-warp
// amortizes the per-warp B-fragment (K/V) smem traffic, the Round-2 bottleneck.
// All fragment LDS conflict-free: stride-68 tiles -> lane addr 4*rt+cq,
// stride-72 V tile -> 8*cq+rt.

namespace {
constexpr int S_LEN = 2048;
constexpr int D     = 64;
constexpr int BM    = 128;
constexpr int BN    = 64;
constexpr int NT    = 128;
constexpr int SPA   = 68;   // stride (floats) for q,k,p tiles
constexpr int SPV   = 72;   // stride (floats) for v tile
constexpr int SMEM_FLOATS = 2 * BM * SPA + BN * SPA + BN * SPV;
constexpr int SMEM_BYTES  = SMEM_FLOATS * (int)sizeof(float);   // 105472 B
}

__device__ __forceinline__ float f2tf32(float x) {
    unsigned u;
    asm("cvt.rna.tf32.f32 %0, %1;" : "=r"(u) : "f"(x));
    return __uint_as_float(u);
}

__device__ __forceinline__ void mma8(float* c, const unsigned* a, const unsigned* b) {
    asm volatile(
        "mma.sync.aligned.m16n8k8.row.col.f32.tf32.tf32.f32 "
        "{%0,%1,%2,%3}, {%4,%5,%6,%7}, {%8,%9}, {%0,%1,%2,%3};"
        : "+f"(c[0]), "+f"(c[1]), "+f"(c[2]), "+f"(c[3])
        : "r"(a[0]), "r"(a[1]), "r"(a[2]), "r"(a[3]), "r"(b[0]), "r"(b[1]));
}

__global__ __launch_bounds__(NT, 1) void mha_tf32_kernel(
    const float* __restrict__ Q, const float* __restrict__ K,
    const float* __restrict__ V, const float* __restrict__ Bias,
    float* __restrict__ O)
{
    extern __shared__ float sh[];
    float* q_sh = sh;                      // [BM][SPA]
    float* p_sh = sh + BM * SPA;           // [BM][SPA]
    float* k_sh = sh + 2 * BM * SPA;       // [BN][SPA]
    float* v_sh = sh + 2 * BM * SPA + BN * SPA;  // [BN][SPV]

    const int tid = threadIdx.x;
    const int w   = tid >> 5;
    const int l   = tid & 31;
    const int rt  = l >> 2;    // 0..7
    const int cq  = l & 3;     // 0..3
    const int m0  = w * 32;    // warp's first query row in tile

    const int q0 = blockIdx.x * BM;
    const size_t base = (size_t)blockIdx.y * S_LEN * D;

    // ---- load Q tile once, scaled by 1/sqrt(D), tf32-rounded ----
    {
        const float4* gq = reinterpret_cast<const float4*>(Q + base + (size_t)q0 * D);
        #pragma unroll
        for (int it = 0; it < (BM * D / 4) / NT; it++) {
            int idx = tid + it * NT;
            int r = idx >> 4, c4 = idx & 15;
            float4 v = gq[idx];
            float4 o;
            o.x = f2tf32(v.x * 0.125f);
            o.y = f2tf32(v.y * 0.125f);
            o.z = f2tf32(v.z * 0.125f);
            o.w = f2tf32(v.w * 0.125f);
            *reinterpret_cast<float4*>(&q_sh[r * SPA + c4 * 4]) = o;
        }
    }

    float c_o[2][8][4];
    float m_st[2][2], l_st[2][2];
    #pragma unroll
    for (int mb = 0; mb < 2; mb++) {
        m_st[mb][0] = -INFINITY; m_st[mb][1] = -INFINITY;
        l_st[mb][0] = 0.f;       l_st[mb][1] = 0.f;
        #pragma unroll
        for (int nb = 0; nb < 8; nb++)
            #pragma unroll
            for (int j = 0; j < 4; j++) c_o[mb][nb][j] = 0.f;
    }

    for (int kt = 0; kt < S_LEN / BN; kt++) {
        const int k0 = kt * BN;

        // ---- bias -> c_s (LDG latency hides under K/V tile fill) ----
        float c_s[2][8][4];
        {
            const float* bb = Bias + (size_t)(q0 + m0 + rt) * S_LEN + k0 + 2 * cq;
            #pragma unroll
            for (int mb = 0; mb < 2; mb++) {
                const float* bm = bb + (size_t)(16 * mb) * S_LEN;
                #pragma unroll
                for (int nb = 0; nb < 8; nb++) {
                    float2 blo = *reinterpret_cast<const float2*>(bm + 8 * nb);
                    float2 bhi = *reinterpret_cast<const float2*>(bm + 8 * S_LEN + 8 * nb);
                    c_s[mb][nb][0] = blo.x; c_s[mb][nb][1] = blo.y;
                    c_s[mb][nb][2] = bhi.x; c_s[mb][nb][3] = bhi.y;
                }
            }
        }

        __syncthreads();   // previous tile's k/v/p reads done
        // ---- load K,V tiles (tf32) ----
        {
            const float4* gk = reinterpret_cast<const float4*>(K + base + (size_t)k0 * D);
            const float4* gv = reinterpret_cast<const float4*>(V + base + (size_t)k0 * D);
            #pragma unroll
            for (int it = 0; it < (BN * D / 4) / NT; it++) {
                int idx = tid + it * NT;
                int r = idx >> 4, c4 = idx & 15;
                float4 kv = gk[idx];
                float4 ko;
                ko.x = f2tf32(kv.x); ko.y = f2tf32(kv.y);
                ko.z = f2tf32(kv.z); ko.w = f2tf32(kv.w);
                *reinterpret_cast<float4*>(&k_sh[r * SPA + c4 * 4]) = ko;
                float4 vv = gv[idx];
                float4 vo;
                vo.x = f2tf32(vv.x); vo.y = f2tf32(vv.y);
                vo.z = f2tf32(vv.z); vo.w = f2tf32(vv.w);
                *reinterpret_cast<float4*>(&v_sh[r * SPV + c4 * 4]) = vo;
            }
        }
        __syncthreads();

        // ---- QK^T: 8 k-steps x (2 m-blocks x 8 n-blocks) ----
        #pragma unroll
        for (int ks = 0; ks < 8; ks++) {
            unsigned a[2][4];
            #pragma unroll
            for (int mb = 0; mb < 2; mb++) {
                const float* qr = &q_sh[(m0 + 16 * mb + rt) * SPA + 8 * ks + cq];
                a[mb][0] = __float_as_uint(qr[0]);
                a[mb][1] = __float_as_uint(qr[8 * SPA]);
                a[mb][2] = __float_as_uint(qr[4]);
                a[mb][3] = __float_as_uint(qr[8 * SPA + 4]);
            }
            #pragma unroll
            for (int nb = 0; nb < 8; nb++) {
                unsigned b[2];
                const float* kr = &k_sh[(8 * nb + rt) * SPA + 8 * ks + cq];
                b[0] = __float_as_uint(kr[0]);
                b[1] = __float_as_uint(kr[4]);
                mma8(c_s[0][nb], a[0], b);
                mma8(c_s[1][nb], a[1], b);
            }
        }

        // ---- online softmax per m-block (4-lane groups, shfl 1,2) ----
        #pragma unroll
        for (int mb = 0; mb < 2; mb++) {
            float mx_lo = -INFINITY, mx_hi = -INFINITY;
            #pragma unroll
            for (int nb = 0; nb < 8; nb++) {
                mx_lo = fmaxf(mx_lo, fmaxf(c_s[mb][nb][0], c_s[mb][nb][1]));
                mx_hi = fmaxf(mx_hi, fmaxf(c_s[mb][nb][2], c_s[mb][nb][3]));
            }
            #pragma unroll
            for (int off = 1; off < 4; off <<= 1) {
                mx_lo = fmaxf(mx_lo, __shfl_xor_sync(0xFFFFFFFFu, mx_lo, off, 32));
                mx_hi = fmaxf(mx_hi, __shfl_xor_sync(0xFFFFFFFFu, mx_hi, off, 32));
            }
            const float mn_lo = fmaxf(m_st[mb][0], mx_lo);
            const float mn_hi = fmaxf(m_st[mb][1], mx_hi);
            const float corr_lo = __expf(m_st[mb][0] - mn_lo);
            const float corr_hi = __expf(m_st[mb][1] - mn_hi);
            float rs_lo = 0.f, rs_hi = 0.f;
            #pragma unroll
            for (int nb = 0; nb < 8; nb++) {
                c_s[mb][nb][0] = __expf(c_s[mb][nb][0] - mn_lo);
                c_s[mb][nb][1] = __expf(c_s[mb][nb][1] - mn_lo);
                c_s[mb][nb][2] = __expf(c_s[mb][nb][2] - mn_hi);
                c_s[mb][nb][3] = __expf(c_s[mb][nb][3] - mn_hi);
                rs_lo += c_s[mb][nb][0] + c_s[mb][nb][1];
                rs_hi += c_s[mb][nb][2] + c_s[mb][nb][3];
            }
            #pragma unroll
            for (int off = 1; off < 4; off <<= 1) {
                rs_lo += __shfl_xor_sync(0xFFFFFFFFu, rs_lo, off, 32);
                rs_hi += __shfl_xor_sync(0xFFFFFFFFu, rs_hi, off, 32);
            }
            l_st[mb][0] = l_st[mb][0] * corr_lo + rs_lo;  m_st[mb][0] = mn_lo;
            l_st[mb][1] = l_st[mb][1] * corr_hi + rs_hi;  m_st[mb][1] = mn_hi;
            #pragma unroll
            for (int nb = 0; nb < 8; nb++) {
                c_o[mb][nb][0] *= corr_lo; c_o[mb][nb][1] *= corr_lo;
                c_o[mb][nb][2] *= corr_hi; c_o[mb][nb][3] *= corr_hi;
            }

            // ---- store P (tf32) to warp-private smem rows ----
            float* pr = &p_sh[(m0 + 16 * mb + rt) * SPA + 2 * cq];
            #pragma unroll
            for (int nb = 0; nb < 8; nb++) {
                float2 lo; lo.x = f2tf32(c_s[mb][nb][0]); lo.y = f2tf32(c_s[mb][nb][1]);
                *reinterpret_cast<float2*>(pr + 8 * nb) = lo;
                float2 hi; hi.x = f2tf32(c_s[mb][nb][2]); hi.y = f2tf32(c_s[mb][nb][3]);
                *reinterpret_cast<float2*>(pr + 8 * SPA + 8 * nb) = hi;
            }
        }
        __syncwarp();

        // ---- PV: acc += P @ V ----
        #pragma unroll
        for (int ks = 0; ks < 8; ks++) {
            unsigned a[2][4];
            #pragma unroll
            for (int mb = 0; mb < 2; mb++) {
                const float* pr = &p_sh[(m0 + 16 * mb + rt) * SPA + 8 * ks + cq];
                a[mb][0] = __float_as_uint(pr[0]);
                a[mb][1] = __float_as_uint(pr[8 * SPA]);
                a[mb][2] = __float_as_uint(pr[4]);
                a[mb][3] = __float_as_uint(pr[8 * SPA + 4]);
            }
            #pragma unroll
            for (int nb = 0; nb < 8; nb++) {
                unsigned b[2];
                const float* vr = &v_sh[(8 * ks + cq) * SPV + 8 * nb + rt];
                b[0] = __float_as_uint(vr[0]);
                b[1] = __float_as_uint(vr[4 * SPV]);
                mma8(c_o[0][nb], a[0], b);
                mma8(c_o[1][nb], a[1], b);
            }
        }
    }

    // ---- normalize, write O ----
    #pragma unroll
    for (int mb = 0; mb < 2; mb++) {
        const float inv_lo = 1.0f / l_st[mb][0];
        const float inv_hi = 1.0f / l_st[mb][1];
        float* orow = O + base + (size_t)(q0 + m0 + 16 * mb + rt) * D + 2 * cq;
        #pragma unroll
        for (int nb = 0; nb < 8; nb++) {
            float2 lo; lo.x = c_o[mb][nb][0] * inv_lo; lo.y = c_o[mb][nb][1] * inv_lo;
            *reinterpret_cast<float2*>(orow + 8 * nb) = lo;
            float2 hi; hi.x = c_o[mb][nb][2] * inv_hi; hi.y = c_o[mb][nb][3] * inv_hi;
            *reinterpret_cast<float2*>(orow + 8 * D + 8 * nb) = hi;
        }
    }
}

extern "C" void kernel_launch(void* const* d_in, const int* in_sizes, int n_in,
                              void* d_out, int out_size) {
    const float* Q    = (const float*)d_in[0];
    const float* K    = (const float*)d_in[1];
    const float* V    = (const float*)d_in[2];
    const float* Bias = (const float*)d_in[3];
    float* O = (float*)d_out;

    const int BH = in_sizes[0] / (S_LEN * D);   // 32 for B=2,H=16

    cudaFuncSetAttribute(mha_tf32_kernel,
                         cudaFuncAttributeMaxDynamicSharedMemorySize, SMEM_BYTES);
    dim3 grid(S_LEN / BM, BH);
    mha_tf32_kernel<<<grid, NT, SMEM_BYTES>>>(Q, K, V, Bias, O);
}